// round 15
// baseline (speedup 1.0000x reference)
#include <cuda_runtime.h>
#include <cuda_fp16.h>
#include <cstdint>

// GroupedHybridFFN: B=4,S=4096,D=2048; E=8 experts of d=256; H=1024
//   e 0..1: KAN (lin -> tanh -> Chebyshev T1..T3 -> poly proj; T0 folded to bias)
//   e 2..7: MLP (w1 -> gelu(tanh) -> w2)
// R15 (= R14 resubmit; prior run hit infra failure): MLP path as cross-stage
//      pipeline: chunk=64, double-buffered W1/W2/ACT, fused loop interleaving
//      stage2(c) with stage1(c+1) — two independent MMA chains per warp.
//      KAN path = R13 verbatim.

#define TILE_HALFS 32768          // 64KB fp16 weight tile

// smem layout (bytes) — MLP view (chunk=64, all double buffered)
#define OFF_B1H   0               // 1024 halfs (mlp b1, whole expert)
#define OFF_X     2048            // 64KB  X tile [128,256] swizzled (512B rows)
#define OFF_W1A   67584           // 32KB  W1 chunk buf A  [64,256] RS512
#define OFF_W1B   100352          // 32KB  W1 chunk buf B
#define OFF_W2A   133120          // 32KB  W2 k-half buf A [256,64] RS128
#define OFF_W2B   165888          // 32KB  W2 k-half buf B
#define OFF_ACT0  198656          // 16KB  act tile [128,64] RS128
#define OFF_ACT1  215040          // 16KB
// KAN view (same block, unchanged from R13)
#define OFF_KWA   67584
#define OFF_KWB   100352
#define OFF_KT    133120          // 3 x 16KB [128,64] (128B rows)
#define SMEM_MAIN 231424

#define NTHREADS  256

static __device__ __align__(128) __half g_B1 [64u * TILE_HALFS];  // [e8][c8]  N128,K256 RS512
static __device__ __align__(128) __half g_B2m[48u * TILE_HALFS];  // [e6][c8]  N256,K128 RS256
static __device__ __align__(128) __half g_B2k[48u * TILE_HALFS];  // [(e*8+c)*3+p] N256,K128 RS256
static __device__ float g_c0[512];

// ---------------- helpers ----------------
__device__ __forceinline__ uint32_t smem_u32(const void* p){
    uint32_t a;
    asm("{ .reg .u64 t; cvta.to.shared.u64 t, %1; cvt.u32.u64 %0, t; }" : "=r"(a) : "l"(p));
    return a;
}
__device__ __forceinline__ void cpa16(uint32_t dst, const void* src){
    asm volatile("cp.async.cg.shared.global [%0], [%1], 16;" :: "r"(dst), "l"(src) : "memory");
}
__device__ __forceinline__ void cp_commit(){ asm volatile("cp.async.commit_group;" ::: "memory"); }
__device__ __forceinline__ void cp_wait0(){ asm volatile("cp.async.wait_group 0;" ::: "memory"); }

__device__ __forceinline__ void ldmx4(uint32_t (&r)[4], uint32_t addr){
    asm volatile("ldmatrix.sync.aligned.m8n8.x4.shared.b16 {%0,%1,%2,%3}, [%4];"
        : "=r"(r[0]), "=r"(r[1]), "=r"(r[2]), "=r"(r[3]) : "r"(addr));
}
__device__ __forceinline__ void mma16816(float (&d)[4], const uint32_t (&a)[4],
                                         uint32_t b0, uint32_t b1){
    asm volatile("mma.sync.aligned.m16n8k16.row.col.f32.f16.f16.f32 "
        "{%0,%1,%2,%3},{%4,%5,%6,%7},{%8,%9},{%0,%1,%2,%3};"
        : "+f"(d[0]), "+f"(d[1]), "+f"(d[2]), "+f"(d[3])
        : "r"(a[0]), "r"(a[1]), "r"(a[2]), "r"(a[3]), "r"(b0), "r"(b1));
}
__device__ __forceinline__ float tanh_fast(float y){
    float e = __expf(2.0f * y);
    return 1.0f - __fdividef(2.0f, e + 1.0f);
}
// exact sigmoid form of tanh-gelu
__device__ __forceinline__ float gelu_fast(float v){
    float v2 = v * v;
    float t  = fmaf(0.044715f, v2, 1.0f);
    float E  = (v * -1.5957691216057308f) * t;
    return __fdividef(v, 1.0f + __expf(E));
}
// contiguous NB-byte stream into smem + commit (256 threads)
template<int NB>
__device__ __forceinline__ void pf_tile(uint32_t sdst, const __half* src, int tid){
#pragma unroll
    for (int i = 0; i < NB / (NTHREADS * 16); i++)
        cpa16(sdst + (uint32_t)(i * NTHREADS + tid) * 16, src + (size_t)(i * NTHREADS + tid) * 8);
    cp_commit();
}
// k-half sub-tile: src [256,128] RS256 -> dst [256,64] RS128 (half h); swizzle-safe
__device__ __forceinline__ void pf_poly_half(uint32_t sdst, const __half* src, int h, int tid){
#pragma unroll
    for (int i = 0; i < 8; i++){
        int idx = i * NTHREADS + tid;            // 2048 granules of 16B
        uint32_t n = (uint32_t)idx >> 3, g = ((uint32_t)idx & 7u) * 16;
        cpa16(sdst + n * 128 + g, src + (size_t)n * 128 + (size_t)h * 64 + g / 2);
    }
    cp_commit();
}

// ---------------- prep: fp32 weights -> fp16 swizzled [N,K] tiles (+ c0 sums) ------
__global__ void __launch_bounds__(256) prep_tiles(
    const float* __restrict__ kan_lin_w, const float* __restrict__ mlp_w1,
    const float* __restrict__ mlp_w2,    const float* __restrict__ kan_poly_w)
{
    extern __shared__ __half sh[];
    int bid = blockIdx.x, tid = threadIdx.x;

    if (bid >= 160){                        // c0: colsum of kan poly W0 (experts 0,1)
        int e = bid - 160;
        const float* p0 = kan_poly_w + (size_t)e * 4 * 1024 * 256;
        float s = 0.f;
        for (int h = 0; h < 1024; h++) s += p0[(size_t)h * 256 + tid];
        g_c0[e * 256 + tid] = s;
        return;
    }

    const float* src; __half* dst;
    uint32_t N, RS, sstr;

    if (bid < 64){                         // B1: B[n,k] = W1[k][c*128+n]
        int e = bid >> 3, c = bid & 7;
        src = (e < 2 ? kan_lin_w + (size_t)e * 256 * 1024
                     : mlp_w1   + (size_t)(e - 2) * 256 * 1024) + c * 128;
        N = 128; RS = 512; sstr = 1024; dst = g_B1 + (size_t)bid * TILE_HALFS;
    } else if (bid < 112){                 // B2m: B[n,k] = W2[c*128+k][n]
        int i = bid - 64; int e = i >> 3, c = i & 7;
        src = mlp_w2 + (size_t)e * 1024 * 256 + (size_t)c * 128 * 256;
        N = 256; RS = 256; sstr = 256; dst = g_B2m + (size_t)i * TILE_HALFS;
    } else {                               // B2k: poly p=1..3
        int i = bid - 112; int e = i / 24; int r = i % 24; int c = r / 3; int p = r % 3;
        src = kan_poly_w + (size_t)e * 4 * 1024 * 256 + (size_t)(p + 1) * 1024 * 256
            + (size_t)c * 128 * 256;
        N = 256; RS = 256; sstr = 256; dst = g_B2k + (size_t)i * TILE_HALFS;
    }
    for (uint32_t idx = tid; idx < TILE_HALFS; idx += 256){
        uint32_t n = idx & (N - 1), k = idx / N;
        uint32_t off = n * RS + ((k * 2) ^ ((n & 7u) << 4));
        sh[off >> 1] = __float2half_rn(src[(size_t)k * sstr + n]);
    }
    __syncthreads();
    const uint4* s4 = (const uint4*)sh;
    uint4* d4 = (uint4*)dst;
    for (uint32_t t = tid; t < TILE_HALFS / 8; t += 256) d4[t] = s4[t];
}

// ---------------- stage-2 GEMM (KAN): acc2 += A[128,KS*16] @ B[256,KS*16]^T --------
template<int KS, int RS>
__device__ __forceinline__ void gemm2_pass(
    float (&acc2)[4][8][4], uint32_t sA, uint32_t sB,
    int m2, int o2, uint32_t lrow, uint32_t lkhi, uint32_t axor)
{
#pragma unroll
    for (int ks = 0; ks < KS; ks++){
        uint32_t kx = ((uint32_t)ks * 32 + lkhi) ^ axor;
        uint32_t a[4][4], b[4][4];
#pragma unroll
        for (int mt = 0; mt < 4; mt++)
            ldmx4(a[mt], sA + (uint32_t)(m2 + mt * 16 + lrow) * RS + kx);
#pragma unroll
        for (int ot = 0; ot < 4; ot++)
            ldmx4(b[ot], sB + (uint32_t)(o2 + ot * 16 + lrow) * RS + kx);
#pragma unroll
        for (int mt = 0; mt < 4; mt++)
#pragma unroll
            for (int ot = 0; ot < 4; ot++){
                mma16816(acc2[mt][ot * 2],     a[mt], b[ot][0], b[ot][2]);
                mma16816(acc2[mt][ot * 2 + 1], a[mt], b[ot][1], b[ot][3]);
            }
    }
}

// ---------------- main fused kernel: 1024 CTAs, 256 threads (8 warps) --------------
__global__ void __launch_bounds__(NTHREADS, 1) ffn_main(
    const float* __restrict__ x,      const float* __restrict__ kan_bias,
    const float* __restrict__ mlp_b1, const float* __restrict__ mlp_b2,
    float* __restrict__ out)
{
    extern __shared__ char smem[];
    uint32_t sb = smem_u32(smem);
    const uint32_t sX = sb + OFF_X;

    int tid = threadIdx.x, wid = tid >> 5, lane = tid & 31;
    int bx = blockIdx.x;
    int e = bx >> 7, tile = bx & 127;          // KAN experts (e<2) first
    int row0 = tile * 128;
    bool is_kan = (e < 2);

    // stage1 grid: 4m x 2n -> warp tile m32 x n32 (chunk N=64)
    int m1 = (wid >> 1) * 32, n1 = (wid & 1) * 32;
    // stage2 grid: 2m x 4o -> warp tile m64 x o64
    int m2 = (wid >> 2) * 64, o2 = (wid & 3) * 64;

    uint32_t lrow = lane & 15;
    uint32_t lkhi = (uint32_t)(lane >> 4) << 4;
    uint32_t axor = (lrow & 7u) << 4;
    uint32_t xr = ((uint32_t)(lane >> 2) & 7u) << 4;

    // ---- first weight prefetch (overlaps X load) ----
    if (is_kan) pf_tile<32768>(sb + OFF_KWA, g_B1 + ((size_t)(e * 8) << 15), tid);
    else        pf_tile<32768>(sb + OFF_W1A, g_B1 + ((size_t)(e * 8) << 15), tid);  // W1(0)

    // ---- X tile [128,256] fp32 -> fp16 swizzled (512B rows) ----
    const float* xp = x + (size_t)row0 * 2048 + e * 256;
#pragma unroll
    for (int it = 0; it < 32; it++){
        int idx = it * NTHREADS + tid;
        int r = idx >> 6, q = idx & 63;
        float4 v = *(const float4*)(xp + (size_t)r * 2048 + q * 4);
        uint32_t off = (uint32_t)r * 512 + (((uint32_t)q * 8) ^ ((r & 7u) << 4));
        half2 h0 = __floats2half2_rn(v.x, v.y);
        half2 h1 = __floats2half2_rn(v.z, v.w);
        *(uint2*)(smem + OFF_X + off) = make_uint2(*(uint32_t*)&h0, *(uint32_t*)&h1);
    }
    if (!is_kan){
        const float* b1p = mlp_b1 + (size_t)(e - 2) * 1024;
        for (int i = tid; i < 1024; i += NTHREADS)
            ((__half*)(smem + OFF_B1H))[i] = __float2half_rn(b1p[i]);
    }

    // ---- output accumulators: m64 x o64 per warp (128 regs) ----
    float acc2[4][8][4];
#pragma unroll
    for (int mt = 0; mt < 4; mt++)
#pragma unroll
        for (int ot = 0; ot < 8; ot++)
#pragma unroll
            for (int i = 0; i < 4; i++) acc2[mt][ot][i] = 0.f;

    if (!is_kan){
        // ================== MLP path: chunk=64, cross-stage pipelined ==================
        const uint32_t sW1b[2] = { sb + OFF_W1A, sb + OFF_W1B };
        const uint32_t sW2b[2] = { sb + OFF_W2A, sb + OFF_W2B };
        const uint32_t sACTb[2] = { sb + OFF_ACT0, sb + OFF_ACT1 };
        const __half* B1e = g_B1  + ((size_t)(e * 8) << 15);
        const __half* B2e = g_B2m + ((size_t)((e - 2) * 8) << 15);
        const __half* b1h = (const __half*)(smem + OFF_B1H);

        // W1 chunk j lives at tile j>>1, half j&1 (32KB contiguous)
        #define W1OFF(j) (((size_t)((j) >> 1) << 15) + ((size_t)((j) & 1) << 14))

        // ---- prologue: stage1(0) standalone -> acts(0) ----
        cp_wait0(); __syncthreads();                       // W1(0) + X ready
        pf_poly_half(sW2b[0], B2e, 0, tid);                // W2(0)
        pf_tile<32768>(sW1b[1], B1e + W1OFF(1), tid);      // W1(1)
        {
            float acc1[2][4][4];
#pragma unroll
            for (int mt = 0; mt < 2; mt++)
#pragma unroll
                for (int nt = 0; nt < 4; nt++)
#pragma unroll
                    for (int i = 0; i < 4; i++) acc1[mt][nt][i] = 0.f;
#pragma unroll
            for (int ks = 0; ks < 16; ks++){
                uint32_t kx = ((uint32_t)ks * 32 + lkhi) ^ axor;
                uint32_t a[2][4], b[2][4];
                ldmx4(a[0], sX + (uint32_t)(m1 + lrow) * 512      + kx);
                ldmx4(a[1], sX + (uint32_t)(m1 + 16 + lrow) * 512 + kx);
                ldmx4(b[0], sW1b[0] + (uint32_t)(n1 + lrow) * 512      + kx);
                ldmx4(b[1], sW1b[0] + (uint32_t)(n1 + 16 + lrow) * 512 + kx);
#pragma unroll
                for (int mt = 0; mt < 2; mt++)
#pragma unroll
                    for (int j = 0; j < 2; j++){
                        mma16816(acc1[mt][j * 2],     a[mt], b[j][0], b[j][2]);
                        mma16816(acc1[mt][j * 2 + 1], a[mt], b[j][1], b[j][3]);
                    }
            }
            // epilogue(0) -> ACT0
#pragma unroll
            for (int mt = 0; mt < 2; mt++)
#pragma unroll
            for (int nt = 0; nt < 4; nt++){
                float* d = acc1[mt][nt];
                int r0 = m1 + mt * 16 + (lane >> 2);
                int ncol = n1 + nt * 8 + (lane & 3) * 2;
                half2 bh = *(const half2*)(b1h + ncol);
                float bb0 = __half2float(__low2half(bh));
                float bb1 = __half2float(__high2half(bh));
                uint32_t cb = ((uint32_t)ncol * 2) ^ xr;
#pragma unroll
                for (int h = 0; h < 2; h++){
                    float g0 = gelu_fast(d[h * 2]     + bb0);
                    float g1 = gelu_fast(d[h * 2 + 1] + bb1);
                    *(half2*)(smem + OFF_ACT0 + (uint32_t)(r0 + h * 8) * 128 + cb)
                        = __floats2half2_rn(g0, g1);
                }
            }
        }

        // ---- main pipelined loop: chunk cc does stage2(cc) fused with stage1(cc+1) ----
        for (int cc = 0; cc < 16; cc++){
            cp_wait0(); __syncthreads();     // W2(cc), W1(cc+1) resident; acts(cc) visible
            if (cc <= 14) pf_poly_half(sW2b[(cc + 1) & 1],
                                       B2e + ((size_t)((cc + 1) >> 1) << 15), (cc + 1) & 1, tid);
            if (cc <= 13) pf_tile<32768>(sW1b[cc & 1], B1e + W1OFF(cc + 2), tid);

            bool do_s1 = (cc < 15);
            uint32_t sA2 = sACTb[cc & 1], sB2 = sW2b[cc & 1], sW1n = sW1b[(cc + 1) & 1];

            float acc1[2][4][4];
#pragma unroll
            for (int mt = 0; mt < 2; mt++)
#pragma unroll
                for (int nt = 0; nt < 4; nt++)
#pragma unroll
                    for (int i = 0; i < 4; i++) acc1[mt][nt][i] = 0.f;

#pragma unroll
            for (int ks2 = 0; ks2 < 4; ks2++){
                uint32_t kx2 = ((uint32_t)ks2 * 32 + lkhi) ^ axor;
                uint32_t a2[4][4], b2[4][4];
#pragma unroll
                for (int mt = 0; mt < 4; mt++)
                    ldmx4(a2[mt], sA2 + (uint32_t)(m2 + mt * 16 + lrow) * 128 + kx2);
#pragma unroll
                for (int ot = 0; ot < 4; ot++)
                    ldmx4(b2[ot], sB2 + (uint32_t)(o2 + ot * 16 + lrow) * 128 + kx2);

#pragma unroll
                for (int j = 0; j < 4; j++){
                    // one stage-1 k-step (independent chain)
                    if (do_s1){
                        uint32_t kx1 = ((uint32_t)(ks2 * 4 + j) * 32 + lkhi) ^ axor;
                        uint32_t a1[2][4], b1f[2][4];
                        ldmx4(a1[0], sX  + (uint32_t)(m1 + lrow) * 512      + kx1);
                        ldmx4(a1[1], sX  + (uint32_t)(m1 + 16 + lrow) * 512 + kx1);
                        ldmx4(b1f[0], sW1n + (uint32_t)(n1 + lrow) * 512      + kx1);
                        ldmx4(b1f[1], sW1n + (uint32_t)(n1 + 16 + lrow) * 512 + kx1);
#pragma unroll
                        for (int mt = 0; mt < 2; mt++)
#pragma unroll
                            for (int jj = 0; jj < 2; jj++){
                                mma16816(acc1[mt][jj * 2],     a1[mt], b1f[jj][0], b1f[jj][2]);
                                mma16816(acc1[mt][jj * 2 + 1], a1[mt], b1f[jj][1], b1f[jj][3]);
                            }
                    }
                    // one o-column of stage-2 MMAs (acc2 chain)
#pragma unroll
                    for (int mt = 0; mt < 4; mt++){
                        mma16816(acc2[mt][j * 2],     a2[mt], b2[j][0], b2[j][2]);
                        mma16816(acc2[mt][j * 2 + 1], a2[mt], b2[j][1], b2[j][3]);
                    }
                }
            }

            if (do_s1){
                // epilogue(cc+1) -> ACT[(cc+1)&1]
                const __half* b1c = b1h + (cc + 1) * 64;
                uint32_t actn = sACTb[(cc + 1) & 1];
#pragma unroll
                for (int mt = 0; mt < 2; mt++)
#pragma unroll
                for (int nt = 0; nt < 4; nt++){
                    float* d = acc1[mt][nt];
                    int r0 = m1 + mt * 16 + (lane >> 2);
                    int ncol = n1 + nt * 8 + (lane & 3) * 2;
                    half2 bh = *(const half2*)(b1c + ncol);
                    float bb0 = __half2float(__low2half(bh));
                    float bb1 = __half2float(__high2half(bh));
                    uint32_t cb = ((uint32_t)ncol * 2) ^ xr;
#pragma unroll
                    for (int h = 0; h < 2; h++){
                        float g0 = gelu_fast(d[h * 2]     + bb0);
                        float g1 = gelu_fast(d[h * 2 + 1] + bb1);
                        *(half2*)(smem + (actn - sb) + (uint32_t)(r0 + h * 8) * 128 + cb)
                            = __floats2half2_rn(g0, g1);
                    }
                }
            }
        }
        #undef W1OFF
    } else {
        // =========================== KAN path (R13 verbatim) ==============================
        const uint32_t sWA = sb + OFF_KWA, sWB = sb + OFF_KWB, sKT = sb + OFF_KT;
        int nk1 = (wid & 1) * 32;
        for (int cc = 0; cc < 16; cc++){
            int c = cc >> 1, hh = cc & 1;
            const __half* poly = g_B2k + ((size_t)((e * 8 + c) * 3) << 15);

            cp_wait0(); __syncthreads();               // W1k(cc) ready; WB free
            pf_poly_half(sWB, poly, hh, tid);          // P1

            float acc1[2][4][4];
#pragma unroll
            for (int mt = 0; mt < 2; mt++)
#pragma unroll
                for (int nt = 0; nt < 4; nt++)
#pragma unroll
                    for (int i = 0; i < 4; i++) acc1[mt][nt][i] = 0.f;
#pragma unroll
            for (int ks = 0; ks < 16; ks++){
                uint32_t kx = ((uint32_t)ks * 32 + lkhi) ^ axor;
                uint32_t a[2][4], b[2][4];
                ldmx4(a[0], sX  + (uint32_t)(m1 + lrow) * 512      + kx);
                ldmx4(a[1], sX  + (uint32_t)(m1 + 16 + lrow) * 512 + kx);
                ldmx4(b[0], sWA + (uint32_t)(nk1 + lrow) * 512      + kx);
                ldmx4(b[1], sWA + (uint32_t)(nk1 + 16 + lrow) * 512 + kx);
#pragma unroll
                for (int mt = 0; mt < 2; mt++)
#pragma unroll
                    for (int j = 0; j < 2; j++){
                        mma16816(acc1[mt][j * 2],     a[mt], b[j][0], b[j][2]);
                        mma16816(acc1[mt][j * 2 + 1], a[mt], b[j][1], b[j][3]);
                    }
            }
#pragma unroll
            for (int mt = 0; mt < 2; mt++)
#pragma unroll
            for (int nt = 0; nt < 4; nt++){
                float* d = acc1[mt][nt];
                int r0 = m1 + mt * 16 + (lane >> 2);
                int ncol = nk1 + nt * 8 + (lane & 3) * 2;
                uint32_t cb = ((uint32_t)ncol * 2) ^ xr;
#pragma unroll
                for (int h = 0; h < 2; h++){
                    float t0 = tanh_fast(d[h * 2]);
                    float t1 = tanh_fast(d[h * 2 + 1]);
                    float u0 = fmaf(2.f * t0, t0, -1.f);
                    float u1 = fmaf(2.f * t1, t1, -1.f);
                    float w0 = fmaf(2.f * t0, u0, -t0);
                    float w1 = fmaf(2.f * t1, u1, -t1);
                    uint32_t ro = (uint32_t)(r0 + h * 8) * 128 + cb;
                    *(half2*)(smem + OFF_KT         + ro) = __floats2half2_rn(t0, t1);
                    *(half2*)(smem + OFF_KT + 16384 + ro) = __floats2half2_rn(u0, u1);
                    *(half2*)(smem + OFF_KT + 32768 + ro) = __floats2half2_rn(w0, w1);
                }
            }
            cp_wait0(); __syncthreads();               // P1 ready; acts visible; WA free
            pf_poly_half(sWA, poly + TILE_HALFS, hh, tid);          // P2
            gemm2_pass<4, 128>(acc2, sKT, sWB, m2, o2, lrow, lkhi, axor);

            cp_wait0(); __syncthreads();               // P2 ready; WB free
            pf_poly_half(sWB, poly + 2 * TILE_HALFS, hh, tid);      // P3
            gemm2_pass<4, 128>(acc2, sKT + 16384, sWA, m2, o2, lrow, lkhi, axor);

            cp_wait0(); __syncthreads();               // P3 ready; WA free
            if (cc < 15){
                int nc = cc + 1;
                pf_tile<32768>(sWA, g_B1 + (((size_t)(e * 8 + (nc >> 1)) << 15)
                                            + ((size_t)(nc & 1) << 14)), tid);
            }
            gemm2_pass<4, 128>(acc2, sKT + 32768, sWB, m2, o2, lrow, lkhi, axor);
        }
    }

    // ---------- final store: acc2 + bias -> gmem fp32 ----------
    float bb[8][2];
#pragma unroll
    for (int blk = 0; blk < 8; blk++){
        int oc = o2 + blk * 8 + (lane & 3) * 2;
        if (is_kan){
            bb[blk][0] = __ldg(kan_bias + e * 256 + oc)     + g_c0[e * 256 + oc];
            bb[blk][1] = __ldg(kan_bias + e * 256 + oc + 1) + g_c0[e * 256 + oc + 1];
        } else {
            bb[blk][0] = __ldg(mlp_b2 + (e - 2) * 256 + oc);
            bb[blk][1] = __ldg(mlp_b2 + (e - 2) * 256 + oc + 1);
        }
    }
#pragma unroll
    for (int mt = 0; mt < 4; mt++)
#pragma unroll
    for (int blk = 0; blk < 8; blk++){
        float* d = acc2[mt][blk];
        int r0 = row0 + m2 + mt * 16 + (lane >> 2);
        int oc = o2 + blk * 8 + (lane & 3) * 2;
        float* op0 = out + (size_t)r0 * 2048 + e * 256 + oc;
        float* op1 = op0 + 8 * 2048;
        op0[0] = d[0] + bb[blk][0];  op0[1] = d[1] + bb[blk][1];
        op1[0] = d[2] + bb[blk][0];  op1[1] = d[3] + bb[blk][1];
    }
}

// ---------------- kernel_launch ----------------
extern "C" void kernel_launch(void* const* d_in, const int* in_sizes, int n_in,
                              void* d_out, int out_size)
{
    const float* x   = (const float*)d_in[0];
    const float* klw = (const float*)d_in[1];
    const float* kpw = (const float*)d_in[2];
    const float* kb  = (const float*)d_in[3];
    const float* w1  = (const float*)d_in[4];
    const float* b1  = (const float*)d_in[5];
    const float* w2  = (const float*)d_in[6];
    const float* b2  = (const float*)d_in[7];
    float* out = (float*)d_out;
    (void)in_sizes; (void)n_in; (void)out_size;

    cudaFuncSetAttribute(prep_tiles, cudaFuncAttributeMaxDynamicSharedMemorySize, 65536);
    cudaFuncSetAttribute(ffn_main,   cudaFuncAttributeMaxDynamicSharedMemorySize, SMEM_MAIN);

    prep_tiles<<<162, 256, 65536>>>(klw, w1, w2, kpw);
    ffn_main<<<1024, NTHREADS, SMEM_MAIN>>>(x, kb, b1, b2, out);
}

// round 17
// speedup vs baseline: 1.0364x; 1.0364x over previous
#include <cuda_runtime.h>
#include <cuda_fp16.h>
#include <cstdint>

// GroupedHybridFFN: B=4,S=4096,D=2048; E=8 experts of d=256; H=1024
//   e 0..1: KAN (lin -> tanh -> Chebyshev T1..T3 -> poly proj; T0 folded to bias)
//   e 2..7: MLP (w1 -> gelu(tanh) -> w2)
// R17 (= R16 resubmit; prior run hit infra failure): R13 base; KAN stage-2 with
//      3-buffer rotation: P1+P2 prefetched together, gemm(t)+gemm(T2)
//      barrier-free back-to-back, P3 reuses the W1k buffer. Syncs/chunk 4->3.
//      MLP path unchanged.

#define TILE_HALFS 32768          // 64KB fp16 weight tile

// smem layout (bytes) — MLP view
#define OFF_B1H   0               // 1024 halfs (mlp b1, whole expert)
#define OFF_X     2048            // 64KB  X tile [128,256] swizzled (512B rows)
#define OFF_WA    67584           // 64KB  weight buffer A (W1 chunk)
#define OFF_WB    133120          // 64KB  weight buffer B (W2 chunk)
#define OFF_ACT   198656          // 32KB  act tile [128,128] (256B rows)
// KAN view (same block): 3 x 32KB weight buffers + 48KB act tiles
#define OFF_KB0   67584
#define OFF_KB1   100352
#define OFF_KB2   133120
#define OFF_KT    165888          // 3 x 16KB [128,64] (128B rows) -> ends 215040
#define SMEM_MAIN 231424

#define NTHREADS  256

static __device__ __align__(128) __half g_B1 [64u * TILE_HALFS];  // [e8][c8]  N128,K256 RS512
static __device__ __align__(128) __half g_B2m[48u * TILE_HALFS];  // [e6][c8]  N256,K128 RS256
static __device__ __align__(128) __half g_B2k[48u * TILE_HALFS];  // [(e*8+c)*3+p] N256,K128 RS256
static __device__ float g_c0[512];

// ---------------- helpers ----------------
__device__ __forceinline__ uint32_t smem_u32(const void* p){
    uint32_t a;
    asm("{ .reg .u64 t; cvta.to.shared.u64 t, %1; cvt.u32.u64 %0, t; }" : "=r"(a) : "l"(p));
    return a;
}
__device__ __forceinline__ void cpa16(uint32_t dst, const void* src){
    asm volatile("cp.async.cg.shared.global [%0], [%1], 16;" :: "r"(dst), "l"(src) : "memory");
}
__device__ __forceinline__ void cp_commit(){ asm volatile("cp.async.commit_group;" ::: "memory"); }
__device__ __forceinline__ void cp_wait0(){ asm volatile("cp.async.wait_group 0;" ::: "memory"); }

__device__ __forceinline__ void ldmx4(uint32_t (&r)[4], uint32_t addr){
    asm volatile("ldmatrix.sync.aligned.m8n8.x4.shared.b16 {%0,%1,%2,%3}, [%4];"
        : "=r"(r[0]), "=r"(r[1]), "=r"(r[2]), "=r"(r[3]) : "r"(addr));
}
__device__ __forceinline__ void mma16816(float (&d)[4], const uint32_t (&a)[4],
                                         uint32_t b0, uint32_t b1){
    asm volatile("mma.sync.aligned.m16n8k16.row.col.f32.f16.f16.f32 "
        "{%0,%1,%2,%3},{%4,%5,%6,%7},{%8,%9},{%0,%1,%2,%3};"
        : "+f"(d[0]), "+f"(d[1]), "+f"(d[2]), "+f"(d[3])
        : "r"(a[0]), "r"(a[1]), "r"(a[2]), "r"(a[3]), "r"(b0), "r"(b1));
}
__device__ __forceinline__ float tanh_fast(float y){
    float e = __expf(2.0f * y);
    return 1.0f - __fdividef(2.0f, e + 1.0f);
}
// exact sigmoid form of tanh-gelu
__device__ __forceinline__ float gelu_fast(float v){
    float v2 = v * v;
    float t  = fmaf(0.044715f, v2, 1.0f);
    float E  = (v * -1.5957691216057308f) * t;
    return __fdividef(v, 1.0f + __expf(E));
}
// contiguous NB-byte stream into smem + commit (256 threads)
template<int NB>
__device__ __forceinline__ void pf_tile(uint32_t sdst, const __half* src, int tid){
#pragma unroll
    for (int i = 0; i < NB / (NTHREADS * 16); i++)
        cpa16(sdst + (uint32_t)(i * NTHREADS + tid) * 16, src + (size_t)(i * NTHREADS + tid) * 8);
    cp_commit();
}
// k-half sub-tile: src [256,128] RS256 -> dst [256,64] RS128 (half h); swizzle-safe
__device__ __forceinline__ void pf_poly_half(uint32_t sdst, const __half* src, int h, int tid){
#pragma unroll
    for (int i = 0; i < 8; i++){
        int idx = i * NTHREADS + tid;            // 2048 granules of 16B
        uint32_t n = (uint32_t)idx >> 3, g = ((uint32_t)idx & 7u) * 16;
        cpa16(sdst + n * 128 + g, src + (size_t)n * 128 + (size_t)h * 64 + g / 2);
    }
    cp_commit();
}

// ---------------- prep: fp32 weights -> fp16 swizzled [N,K] tiles (+ c0 sums) ------
__global__ void __launch_bounds__(256) prep_tiles(
    const float* __restrict__ kan_lin_w, const float* __restrict__ mlp_w1,
    const float* __restrict__ mlp_w2,    const float* __restrict__ kan_poly_w)
{
    extern __shared__ __half sh[];
    int bid = blockIdx.x, tid = threadIdx.x;

    if (bid >= 160){                        // c0: colsum of kan poly W0 (experts 0,1)
        int e = bid - 160;
        const float* p0 = kan_poly_w + (size_t)e * 4 * 1024 * 256;
        float s = 0.f;
        for (int h = 0; h < 1024; h++) s += p0[(size_t)h * 256 + tid];
        g_c0[e * 256 + tid] = s;
        return;
    }

    const float* src; __half* dst;
    uint32_t N, RS, sstr;

    if (bid < 64){                         // B1: B[n,k] = W1[k][c*128+n]
        int e = bid >> 3, c = bid & 7;
        src = (e < 2 ? kan_lin_w + (size_t)e * 256 * 1024
                     : mlp_w1   + (size_t)(e - 2) * 256 * 1024) + c * 128;
        N = 128; RS = 512; sstr = 1024; dst = g_B1 + (size_t)bid * TILE_HALFS;
    } else if (bid < 112){                 // B2m: B[n,k] = W2[c*128+k][n]
        int i = bid - 64; int e = i >> 3, c = i & 7;
        src = mlp_w2 + (size_t)e * 1024 * 256 + (size_t)c * 128 * 256;
        N = 256; RS = 256; sstr = 256; dst = g_B2m + (size_t)i * TILE_HALFS;
    } else {                               // B2k: poly p=1..3
        int i = bid - 112; int e = i / 24; int r = i % 24; int c = r / 3; int p = r % 3;
        src = kan_poly_w + (size_t)e * 4 * 1024 * 256 + (size_t)(p + 1) * 1024 * 256
            + (size_t)c * 128 * 256;
        N = 256; RS = 256; sstr = 256; dst = g_B2k + (size_t)i * TILE_HALFS;
    }
    for (uint32_t idx = tid; idx < TILE_HALFS; idx += 256){
        uint32_t n = idx & (N - 1), k = idx / N;
        uint32_t off = n * RS + ((k * 2) ^ ((n & 7u) << 4));
        sh[off >> 1] = __float2half_rn(src[(size_t)k * sstr + n]);
    }
    __syncthreads();
    const uint4* s4 = (const uint4*)sh;
    uint4* d4 = (uint4*)dst;
    for (uint32_t t = tid; t < TILE_HALFS / 8; t += 256) d4[t] = s4[t];
}

// ---------------- stage-2 GEMM: acc2 += A[128,KS*16] @ B[256,KS*16]^T --------------
// 8-warp grid 2m x 4o -> warp tile m64 x o64. RS = row stride bytes of both tiles.
template<int KS, int RS>
__device__ __forceinline__ void gemm2_pass(
    float (&acc2)[4][8][4], uint32_t sA, uint32_t sB,
    int m2, int o2, uint32_t lrow, uint32_t lkhi, uint32_t axor)
{
#pragma unroll
    for (int ks = 0; ks < KS; ks++){
        uint32_t kx = ((uint32_t)ks * 32 + lkhi) ^ axor;
        uint32_t a[4][4], b[4][4];
#pragma unroll
        for (int mt = 0; mt < 4; mt++)
            ldmx4(a[mt], sA + (uint32_t)(m2 + mt * 16 + lrow) * RS + kx);
#pragma unroll
        for (int ot = 0; ot < 4; ot++)
            ldmx4(b[ot], sB + (uint32_t)(o2 + ot * 16 + lrow) * RS + kx);
#pragma unroll
        for (int mt = 0; mt < 4; mt++)
#pragma unroll
            for (int ot = 0; ot < 4; ot++){
                mma16816(acc2[mt][ot * 2],     a[mt], b[ot][0], b[ot][2]);
                mma16816(acc2[mt][ot * 2 + 1], a[mt], b[ot][1], b[ot][3]);
            }
    }
}

// ---------------- main fused kernel: 1024 CTAs, 256 threads (8 warps) --------------
__global__ void __launch_bounds__(NTHREADS, 1) ffn_main(
    const float* __restrict__ x,      const float* __restrict__ kan_bias,
    const float* __restrict__ mlp_b1, const float* __restrict__ mlp_b2,
    float* __restrict__ out)
{
    extern __shared__ char smem[];
    uint32_t sb = smem_u32(smem);
    const uint32_t sX = sb + OFF_X;

    int tid = threadIdx.x, wid = tid >> 5, lane = tid & 31;
    int bx = blockIdx.x;
    int e = bx >> 7, tile = bx & 127;          // KAN experts (e<2) first
    int row0 = tile * 128;
    bool is_kan = (e < 2);

    // stage1 grid: 4m x 2n -> warp tile m32 x n{64 mlp | 32 kan}
    int m1 = (wid >> 1) * 32, nhalf = wid & 1;
    // stage2 grid: 2m x 4o -> warp tile m64 x o64
    int m2 = (wid >> 2) * 64, o2 = (wid & 3) * 64;

    uint32_t lrow = lane & 15;
    uint32_t lkhi = (uint32_t)(lane >> 4) << 4;
    uint32_t axor = (lrow & 7u) << 4;
    uint32_t xr = ((uint32_t)(lane >> 2) & 7u) << 4;

    // ---- first weight prefetch (overlaps X load) ----
    if (is_kan) pf_tile<32768>(sb + OFF_KB0, g_B1 + ((size_t)(e * 8) << 15), tid);
    else        pf_tile<65536>(sb + OFF_WA,  g_B1 + ((size_t)(e * 8) << 15), tid);

    // ---- X tile [128,256] fp32 -> fp16 swizzled (512B rows) ----
    const float* xp = x + (size_t)row0 * 2048 + e * 256;
#pragma unroll
    for (int it = 0; it < 32; it++){
        int idx = it * NTHREADS + tid;
        int r = idx >> 6, q = idx & 63;
        float4 v = *(const float4*)(xp + (size_t)r * 2048 + q * 4);
        uint32_t off = (uint32_t)r * 512 + (((uint32_t)q * 8) ^ ((r & 7u) << 4));
        half2 h0 = __floats2half2_rn(v.x, v.y);
        half2 h1 = __floats2half2_rn(v.z, v.w);
        *(uint2*)(smem + OFF_X + off) = make_uint2(*(uint32_t*)&h0, *(uint32_t*)&h1);
    }
    if (!is_kan){
        const float* b1p = mlp_b1 + (size_t)(e - 2) * 1024;
        for (int i = tid; i < 1024; i += NTHREADS)
            ((__half*)(smem + OFF_B1H))[i] = __float2half_rn(b1p[i]);
    }

    // ---- output accumulators: m64 x o64 per warp (128 regs) ----
    float acc2[4][8][4];
#pragma unroll
    for (int mt = 0; mt < 4; mt++)
#pragma unroll
        for (int ot = 0; ot < 8; ot++)
#pragma unroll
            for (int i = 0; i < 4; i++) acc2[mt][ot][i] = 0.f;

    if (!is_kan){
        // =========================== MLP path (chunks of 128 H, = R13) ====================
        const uint32_t sWA = sb + OFF_WA, sWB = sb + OFF_WB, sACT = sb + OFF_ACT;
        int n1 = nhalf * 64;
        for (int c = 0; c < 8; c++){
            cp_wait0(); __syncthreads();               // W1(c) ready; WB free
            pf_tile<65536>(sWB, g_B2m + ((size_t)((e - 2) * 8 + c) << 15), tid);

            // stage 1: m32 x n64, K=256
            float acc1[2][8][4];
#pragma unroll
            for (int mt = 0; mt < 2; mt++)
#pragma unroll
                for (int nt = 0; nt < 8; nt++)
#pragma unroll
                    for (int i = 0; i < 4; i++) acc1[mt][nt][i] = 0.f;
#pragma unroll
            for (int ks = 0; ks < 16; ks++){
                uint32_t kx = ((uint32_t)ks * 32 + lkhi) ^ axor;
                uint32_t a[2][4], b[2][4];
                ldmx4(a[0], sX + (uint32_t)(m1 + lrow) * 512      + kx);
                ldmx4(a[1], sX + (uint32_t)(m1 + 16 + lrow) * 512 + kx);
#pragma unroll
                for (int half = 0; half < 2; half++){
                    ldmx4(b[0], sWA + (uint32_t)(n1 + half * 32 + lrow) * 512      + kx);
                    ldmx4(b[1], sWA + (uint32_t)(n1 + half * 32 + 16 + lrow) * 512 + kx);
#pragma unroll
                    for (int mt = 0; mt < 2; mt++)
#pragma unroll
                        for (int j = 0; j < 2; j++){
                            mma16816(acc1[mt][half * 4 + j * 2],     a[mt], b[j][0], b[j][2]);
                            mma16816(acc1[mt][half * 4 + j * 2 + 1], a[mt], b[j][1], b[j][3]);
                        }
                }
            }
            // epilogue 1: gelu -> act tile [128,128] RS256
            {
                const __half* b1h = (const __half*)(smem + OFF_B1H) + c * 128;
#pragma unroll
                for (int mt = 0; mt < 2; mt++)
#pragma unroll
                for (int nt = 0; nt < 8; nt++){
                    float* d = acc1[mt][nt];
                    int r0 = m1 + mt * 16 + (lane >> 2);
                    int ncol = n1 + nt * 8 + (lane & 3) * 2;
                    half2 bh = *(const half2*)(b1h + ncol);
                    float bb0 = __half2float(__low2half(bh));
                    float bb1 = __half2float(__high2half(bh));
                    uint32_t cb = ((uint32_t)ncol * 2) ^ xr;
#pragma unroll
                    for (int h = 0; h < 2; h++){
                        float g0 = gelu_fast(d[h * 2]     + bb0);
                        float g1 = gelu_fast(d[h * 2 + 1] + bb1);
                        *(half2*)(smem + OFF_ACT + (uint32_t)(r0 + h * 8) * 256 + cb)
                            = __floats2half2_rn(g0, g1);
                    }
                }
            }
            cp_wait0(); __syncthreads();               // W2(c) ready; acts visible; WA free
            if (c < 7) pf_tile<65536>(sWA, g_B1 + ((size_t)(e * 8 + c + 1) << 15), tid);
            gemm2_pass<8, 256>(acc2, sACT, sWB, m2, o2, lrow, lkhi, axor);
        }
    } else {
        // =========================== KAN path: 3-buffer rotation =========================
        const uint32_t sKT = sb + OFF_KT;
        uint32_t sB3[3] = { sb + OFF_KB0, sb + OFF_KB1, sb + OFF_KB2 };
        int iw = 0;                                 // buffer holding W1k(cc)
        int n1 = nhalf * 32;
        for (int cc = 0; cc < 16; cc++){
            int c = cc >> 1, hh = cc & 1;
            const __half* poly = g_B2k + ((size_t)((e * 8 + c) * 3) << 15);
            int ia = (iw + 1 < 3) ? iw + 1 : iw - 2;
            int ib = (iw + 2 < 3) ? iw + 2 : iw - 1;

            cp_wait0(); __syncthreads();            // W1k(cc) ready; ia/ib free
            pf_poly_half(sB3[ia], poly,              hh, tid);   // P1
            pf_poly_half(sB3[ib], poly + TILE_HALFS, hh, tid);   // P2

            // stage 1: m32 x n32, K=256 (reads sB3[iw])
            float acc1[2][4][4];
#pragma unroll
            for (int mt = 0; mt < 2; mt++)
#pragma unroll
                for (int nt = 0; nt < 4; nt++)
#pragma unroll
                    for (int i = 0; i < 4; i++) acc1[mt][nt][i] = 0.f;
#pragma unroll
            for (int ks = 0; ks < 16; ks++){
                uint32_t kx = ((uint32_t)ks * 32 + lkhi) ^ axor;
                uint32_t a[2][4], b[2][4];
                ldmx4(a[0], sX       + (uint32_t)(m1 + lrow) * 512      + kx);
                ldmx4(a[1], sX       + (uint32_t)(m1 + 16 + lrow) * 512 + kx);
                ldmx4(b[0], sB3[iw]  + (uint32_t)(n1 + lrow) * 512      + kx);
                ldmx4(b[1], sB3[iw]  + (uint32_t)(n1 + 16 + lrow) * 512 + kx);
#pragma unroll
                for (int mt = 0; mt < 2; mt++)
#pragma unroll
                    for (int j = 0; j < 2; j++){
                        mma16816(acc1[mt][j * 2],     a[mt], b[j][0], b[j][2]);
                        mma16816(acc1[mt][j * 2 + 1], a[mt], b[j][1], b[j][3]);
                    }
            }
            // epilogue 1: t, T2, T3 -> 3 tiles [128,64] RS128
#pragma unroll
            for (int mt = 0; mt < 2; mt++)
#pragma unroll
            for (int nt = 0; nt < 4; nt++){
                float* d = acc1[mt][nt];
                int r0 = m1 + mt * 16 + (lane >> 2);
                int ncol = n1 + nt * 8 + (lane & 3) * 2;
                uint32_t cb = ((uint32_t)ncol * 2) ^ xr;
#pragma unroll
                for (int h = 0; h < 2; h++){
                    float t0 = tanh_fast(d[h * 2]);
                    float t1 = tanh_fast(d[h * 2 + 1]);
                    float u0 = fmaf(2.f * t0, t0, -1.f);
                    float u1 = fmaf(2.f * t1, t1, -1.f);
                    float w0 = fmaf(2.f * t0, u0, -t0);
                    float w1 = fmaf(2.f * t1, u1, -t1);
                    uint32_t ro = (uint32_t)(r0 + h * 8) * 128 + cb;
                    *(half2*)(smem + OFF_KT         + ro) = __floats2half2_rn(t0, t1);
                    *(half2*)(smem + OFF_KT + 16384 + ro) = __floats2half2_rn(u0, u1);
                    *(half2*)(smem + OFF_KT + 32768 + ro) = __floats2half2_rn(w0, w1);
                }
            }
            cp_wait0(); __syncthreads();            // P1+P2 ready; acts visible; iw free
            pf_poly_half(sB3[iw], poly + 2 * TILE_HALFS, hh, tid);  // P3 -> old W1k buf

            gemm2_pass<4, 128>(acc2, sKT,         sB3[ia], m2, o2, lrow, lkhi, axor); // t @P1
            gemm2_pass<4, 128>(acc2, sKT + 16384, sB3[ib], m2, o2, lrow, lkhi, axor); // T2@P2

            cp_wait0(); __syncthreads();            // P3 ready; ia free (gemm t done)
            if (cc < 15){
                int nc = cc + 1;
                pf_tile<32768>(sB3[ia], g_B1 + (((size_t)(e * 8 + (nc >> 1)) << 15)
                                                + ((size_t)(nc & 1) << 14)), tid);  // W1k(cc+1)
            }
            gemm2_pass<4, 128>(acc2, sKT + 32768, sB3[iw], m2, o2, lrow, lkhi, axor); // T3@P3
            iw = ia;                                 // next W1k buffer
        }
    }

    // ---------- final store: acc2 + bias -> gmem fp32 ----------
    float bb[8][2];
#pragma unroll
    for (int blk = 0; blk < 8; blk++){
        int oc = o2 + blk * 8 + (lane & 3) * 2;
        if (is_kan){
            bb[blk][0] = __ldg(kan_bias + e * 256 + oc)     + g_c0[e * 256 + oc];
            bb[blk][1] = __ldg(kan_bias + e * 256 + oc + 1) + g_c0[e * 256 + oc + 1];
        } else {
            bb[blk][0] = __ldg(mlp_b2 + (e - 2) * 256 + oc);
            bb[blk][1] = __ldg(mlp_b2 + (e - 2) * 256 + oc + 1);
        }
    }
#pragma unroll
    for (int mt = 0; mt < 4; mt++)
#pragma unroll
    for (int blk = 0; blk < 8; blk++){
        float* d = acc2[mt][blk];
        int r0 = row0 + m2 + mt * 16 + (lane >> 2);
        int oc = o2 + blk * 8 + (lane & 3) * 2;
        float* op0 = out + (size_t)r0 * 2048 + e * 256 + oc;
        float* op1 = op0 + 8 * 2048;
        op0[0] = d[0] + bb[blk][0];  op0[1] = d[1] + bb[blk][1];
        op1[0] = d[2] + bb[blk][0];  op1[1] = d[3] + bb[blk][1];
    }
}

// ---------------- kernel_launch ----------------
extern "C" void kernel_launch(void* const* d_in, const int* in_sizes, int n_in,
                              void* d_out, int out_size)
{
    const float* x   = (const float*)d_in[0];
    const float* klw = (const float*)d_in[1];
    const float* kpw = (const float*)d_in[2];
    const float* kb  = (const float*)d_in[3];
    const float* w1  = (const float*)d_in[4];
    const float* b1  = (const float*)d_in[5];
    const float* w2  = (const float*)d_in[6];
    const float* b2  = (const float*)d_in[7];
    float* out = (float*)d_out;
    (void)in_sizes; (void)n_in; (void)out_size;

    cudaFuncSetAttribute(prep_tiles, cudaFuncAttributeMaxDynamicSharedMemorySize, 65536);
    cudaFuncSetAttribute(ffn_main,   cudaFuncAttributeMaxDynamicSharedMemorySize, SMEM_MAIN);

    prep_tiles<<<162, 256, 65536>>>(klw, w1, w2, kpw);
    ffn_main<<<1024, NTHREADS, SMEM_MAIN>>>(x, kb, b1, b2, out);
}